// round 12
// baseline (speedup 1.0000x reference)
#include <cuda_runtime.h>
#include <math.h>

// SparseDimAttention, GB300 sm_103a — persistent warp-specialized pipeline.
// 128 CTAs x 512 thr, 1 CTA/SM (128KB smem), 4 batches per CTA.
// Group B (warps 8-15): streams batch j+1's scores from DRAM into sc2[(j+1)&1] (+min/max).
// Group A (warps 0-7): for batch j: linear-bin exact top-K -> weights in wb ->
//                      ph5 weighted sum (x[j] re-read from L2) -> inline head -> out.
// Named barriers: id1 = group A (256 thr), id2 = group B (256 thr), id0 = step boundary.

constexpr int Ll = 33, Dd = 4096, Pp = 64, Kk = 512, Hh = 128, Bb = 512;
constexpr int BINS = 1024;
constexpr int GRID = 128, GPB = Bb / GRID;   // 4 batches per CTA
#define NTM 512
constexpr int NA = 256;                      // threads per group
constexpr int CHA  = Dd / NA;                // 16
constexpr int BPTA = BINS / NA;              // 4
constexpr int SMEM_BYTES = 128 * 1024;       // forces 1 CTA/SM

#define BARA() asm volatile("bar.sync 1, 256;" ::: "memory")
#define BARB() asm volatile("bar.sync 2, 256;" ::: "memory")

__device__ __forceinline__ unsigned int fkey(float f) {
    unsigned int u = __float_as_uint(f);
    return u ^ ((u & 0x80000000u) ? 0xFFFFFFFFu : 0x80000000u); // ascending monotonic
}

__global__ void __launch_bounds__(NTM, 1) mega_kernel(
    const float* __restrict__ x, const float* __restrict__ Wp,
    const float* __restrict__ bp, const float* __restrict__ ws,
    const float* __restrict__ bsc, const float* __restrict__ gamma,
    const float* __restrict__ beta, const float* __restrict__ W1,
    const float* __restrict__ b1, const float* __restrict__ W2,
    const float* __restrict__ b2, float* __restrict__ out)
{
    extern __shared__ float dyn[];
    float* sc2  = dyn;                        // [2][4096] scores (double buffer)
    float* wb   = dyn + 2 * Dd;               // [4096] weights
    int*   hist = (int*)(wb + Dd);            // [1024]
    float* sW1  = (float*)(hist + BINS);      // [8192]
    float* sWp  = sW1 + Hh * Pp;              // [2112]
    float* sbp  = sWp + Pp * Ll;              // [64]
    float* sg   = sbp + Pp;                   // [64]
    float* sbe  = sg + Pp;                    // [64]
    float* sb1  = sbe + Pp;                   // [128]
    float* sW2  = sb1 + Hh;                   // [256]
    float* yv   = sW2 + 2 * Hh;               // [33]

    __shared__ float v[Ll];
    __shared__ float redA[8];
    __shared__ int   wsumA[8];
    __shared__ float redmxB[8], redmnB[8];
    __shared__ float zz[Pp];
    __shared__ float s_c, s_invZ;
    __shared__ float s_lo2[2], s_sc2[2], s_m2[2];
    __shared__ int   s_thr, s_rem, s_cnt, s_T;

    const int tid = threadIdx.x;
    const int lane = tid & 31, wid = tid >> 5;
    const bool isA = (wid < 8);
    const int tA = tid;            // 0..255 when isA
    const int tB = tid - NA;       // 0..255 when !isA
    const int widB = wid - 8;

    // ---- one-time staging: head weights + folded score projection ----
    for (int i = tid; i < Hh * Pp; i += NTM) sW1[i] = W1[i];
    for (int i = tid; i < Pp * Ll; i += NTM) sWp[i] = Wp[i];
    if (tid < 2 * Hh) sW2[tid] = W2[tid];
    if (tid < Pp) { sbp[tid] = bp[tid]; sg[tid] = gamma[tid]; sbe[tid] = beta[tid]; }
    if (tid < Hh) sb1[tid] = b1[tid];
    if (tid < Ll) {
        float a = 0.f;
        #pragma unroll
        for (int p = 0; p < Pp; ++p) a = fmaf(ws[p], Wp[p * Ll + tid], a);
        v[tid] = a;
    } else if (tid == Ll) {
        float a = bsc[0];
        #pragma unroll
        for (int p = 0; p < Pp; ++p) a = fmaf(ws[p], bp[p], a);
        s_c = a;
    }
    __syncthreads();

    const float4* __restrict__ xall = reinterpret_cast<const float4*>(x);
    const size_t xstride = (size_t)Ll * (Dd / 4);
    const int b0 = blockIdx.x * GPB;

    for (int step = 0; step <= GPB; ++step) {
        if (!isA) {
            // ================= GROUP B: stream batch (b0+step) =================
            if (step < GPB) {
                const int buf = step & 1;
                const float4* __restrict__ xb4 = xall + (size_t)(b0 + step) * xstride;
                float* sc = sc2 + buf * Dd;
                const float cc = s_c;
                float4 a0 = make_float4(cc, cc, cc, cc);
                float4 a1 = a0, a2 = a0, a3 = a0;
                #pragma unroll 3
                for (int l = 0; l < Ll; ++l) {
                    const float vl = v[l];
                    const float4* row = xb4 + (size_t)l * (Dd / 4);
                    float4 x0 = row[tB];
                    float4 x1 = row[NA + tB];
                    float4 x2 = row[2 * NA + tB];
                    float4 x3 = row[3 * NA + tB];
                    a0.x = fmaf(vl, x0.x, a0.x); a0.y = fmaf(vl, x0.y, a0.y);
                    a0.z = fmaf(vl, x0.z, a0.z); a0.w = fmaf(vl, x0.w, a0.w);
                    a1.x = fmaf(vl, x1.x, a1.x); a1.y = fmaf(vl, x1.y, a1.y);
                    a1.z = fmaf(vl, x1.z, a1.z); a1.w = fmaf(vl, x1.w, a1.w);
                    a2.x = fmaf(vl, x2.x, a2.x); a2.y = fmaf(vl, x2.y, a2.y);
                    a2.z = fmaf(vl, x2.z, a2.z); a2.w = fmaf(vl, x2.w, a2.w);
                    a3.x = fmaf(vl, x3.x, a3.x); a3.y = fmaf(vl, x3.y, a3.y);
                    a3.z = fmaf(vl, x3.z, a3.z); a3.w = fmaf(vl, x3.w, a3.w);
                }
                float4* sc4 = reinterpret_cast<float4*>(sc);
                sc4[tB]          = a0;
                sc4[NA + tB]     = a1;
                sc4[2 * NA + tB] = a2;
                sc4[3 * NA + tB] = a3;
                float mx = fmaxf(fmaxf(a0.x, a0.y), fmaxf(a0.z, a0.w));
                mx = fmaxf(mx, fmaxf(fmaxf(a1.x, a1.y), fmaxf(a1.z, a1.w)));
                mx = fmaxf(mx, fmaxf(fmaxf(a2.x, a2.y), fmaxf(a2.z, a2.w)));
                mx = fmaxf(mx, fmaxf(fmaxf(a3.x, a3.y), fmaxf(a3.z, a3.w)));
                float mn = fminf(fminf(a0.x, a0.y), fminf(a0.z, a0.w));
                mn = fminf(mn, fminf(fminf(a1.x, a1.y), fminf(a1.z, a1.w)));
                mn = fminf(mn, fminf(fminf(a2.x, a2.y), fminf(a2.z, a2.w)));
                mn = fminf(mn, fminf(fminf(a3.x, a3.y), fminf(a3.z, a3.w)));
                #pragma unroll
                for (int o = 16; o > 0; o >>= 1) {
                    mx = fmaxf(mx, __shfl_xor_sync(0xFFFFFFFFu, mx, o));
                    mn = fminf(mn, __shfl_xor_sync(0xFFFFFFFFu, mn, o));
                }
                if (lane == 0) { redmxB[widB] = mx; redmnB[widB] = mn; }
                BARB();
                if (widB == 0 && lane < 8) {
                    float mx2 = redmxB[lane], mn2 = redmnB[lane];
                    #pragma unroll
                    for (int o = 4; o > 0; o >>= 1) {
                        mx2 = fmaxf(mx2, __shfl_xor_sync(0x000000FFu, mx2, o));
                        mn2 = fminf(mn2, __shfl_xor_sync(0x000000FFu, mn2, o));
                    }
                    if (lane == 0) {
                        s_m2[buf] = mx2; s_lo2[buf] = mn2;
                        const float r = mx2 - mn2;
                        s_sc2[buf] = (r > 0.f) ? ((float)(BINS - 1) / r) : 0.f;
                    }
                }
            }
        } else {
            // ================= GROUP A: process batch (b0+step-1) =================
            if (step >= 1) {
                const int j = step - 1;
                const int buf = j & 1;
                const float* sc = sc2 + buf * Dd;
                const float lo = s_lo2[buf], scale = s_sc2[buf], mm = s_m2[buf];

                // zero hist + tie counter
                #pragma unroll
                for (int q = 0; q < BPTA; ++q) hist[q * NA + tA] = 0;
                if (tA == 0) s_cnt = 0;
                BARA();

                // value-uniform histogram
                #pragma unroll
                for (int it = 0; it < CHA; ++it) {
                    const float s = sc[it * NA + tA];
                    int bin = (int)((s - lo) * scale);
                    bin = min(BINS - 1, max(0, bin));
                    atomicAdd(&hist[bin], 1);
                }
                BARA();

                // suffix scan: hist[i] = #elements with bin >= i
                {
                    const int base = tA * BPTA;
                    int c[BPTA];
                    #pragma unroll
                    for (int q = 0; q < BPTA; ++q) c[q] = hist[base + q];
                    #pragma unroll
                    for (int q = BPTA - 2; q >= 0; --q) c[q] += c[q + 1];
                    int inc = c[0];
                    #pragma unroll
                    for (int o = 1; o < 32; o <<= 1) {
                        int t = __shfl_up_sync(0xFFFFFFFFu, inc, o);
                        if (lane >= o) inc += t;
                    }
                    if (lane == 31) wsumA[wid] = inc;
                    BARA();
                    if (tA < 8) {
                        int w = wsumA[tA];
                        int iw = w;
                        #pragma unroll
                        for (int o = 1; o < 8; o <<= 1) {
                            int t = __shfl_up_sync(0x000000FFu, iw, o);
                            if (tA >= o) iw += t;
                        }
                        wsumA[tA] = iw - w;     // exclusive warp offset
                        if (tA == 7) s_T = iw;  // grand total
                    }
                    BARA();
                    const int S = s_T - (wsumA[wid] + inc);
                    #pragma unroll
                    for (int q = 0; q < BPTA; ++q) hist[base + q] = S + c[q];
                }
                BARA();

                // threshold bin
                #pragma unroll
                for (int q = 0; q < BPTA; ++q) {
                    const int i = tA * BPTA + q;
                    const int hv = hist[i];
                    const int nx = (i < BINS - 1) ? hist[i + 1] : 0;
                    if (hv >= Kk && nx < Kk) { s_thr = i; s_rem = Kk - nx; }
                }
                BARA();
                const int thr = s_thr, rem = s_rem;

                // tie list (reuse hist)
                #pragma unroll
                for (int it = 0; it < CHA; ++it) {
                    const int d = it * NA + tA;
                    int bin = (int)((sc[d] - lo) * scale);
                    bin = min(BINS - 1, max(0, bin));
                    if (bin == thr) {
                        int pos = atomicAdd(&s_cnt, 1);
                        if (pos < BINS) hist[pos] = d;
                    }
                }
                BARA();
                const int cnt = s_cnt;
                const bool fast = (cnt <= BINS);

                // weights -> wb (sc stays read-only; disjoint writers)
                float zp = 0.f;
                if (fast) {
                    #pragma unroll
                    for (int rep = 0; rep < BPTA; ++rep) {   // ties: rank by (key desc, idx asc)
                        const int i = rep * NA + tA;
                        if (i < cnt) {
                            const int d = hist[i];
                            const float s = sc[d];
                            const unsigned int ke = fkey(s);
                            int rank = 0;
                            for (int j2 = 0; j2 < cnt; ++j2) {
                                const int d2 = hist[j2];
                                const unsigned int k2 = fkey(sc[d2]);
                                rank += (k2 > ke) || (k2 == ke && d2 < d);
                            }
                            const float w = (rank < rem) ? expf(s - mm) : 0.f;
                            wb[d] = w; zp += w;
                        }
                    }
                    #pragma unroll
                    for (int it = 0; it < CHA; ++it) {       // non-ties
                        const int d = it * NA + tA;
                        const float s = sc[d];
                        int bin = (int)((s - lo) * scale);
                        bin = min(BINS - 1, max(0, bin));
                        if (bin > thr)      { const float w = expf(s - mm); wb[d] = w; zp += w; }
                        else if (bin < thr) { wb[d] = 0.f; }
                    }
                } else {  // exact fallback (degenerate data only)
                    #pragma unroll
                    for (int it = 0; it < CHA; ++it) {
                        const int d = it * NA + tA;
                        const float s = sc[d];
                        int bin = (int)((s - lo) * scale);
                        bin = min(BINS - 1, max(0, bin));
                        if (bin > thr)      { const float w = expf(s - mm); wb[d] = w; zp += w; }
                        else if (bin < thr) { wb[d] = 0.f; }
                        else {
                            const unsigned int ke = fkey(s);
                            int rank = 0;
                            for (int d2 = 0; d2 < Dd; ++d2) {
                                const float s2 = sc[d2];
                                int b2i = (int)((s2 - lo) * scale);
                                b2i = min(BINS - 1, max(0, b2i));
                                if (b2i == thr) {
                                    const unsigned int k2 = fkey(s2);
                                    rank += (k2 > ke) || (k2 == ke && d2 < d);
                                }
                            }
                            const float w = (rank < rem) ? expf(s - mm) : 0.f;
                            wb[d] = w; zp += w;
                        }
                    }
                }
                #pragma unroll
                for (int o = 16; o > 0; o >>= 1) zp += __shfl_xor_sync(0xFFFFFFFFu, zp, o);
                if (lane == 0) redA[wid] = zp;
                BARA();
                if (tA < 8) {
                    zp = redA[tA];
                    #pragma unroll
                    for (int o = 4; o > 0; o >>= 1) zp += __shfl_xor_sync(0x000000FFu, zp, o);
                    if (tA == 0) s_invZ = 1.f / zp;
                }
                BARA();

                // ph5: y[l] = invZ * sum_d wb[d]*x[b,l,d]  (x slice re-read from L2)
                {
                    const float invZ = s_invZ;
                    const float4* __restrict__ xb4 = xall + (size_t)(b0 + j) * xstride;
                    const float4* wb4 = reinterpret_cast<const float4*>(wb);
                    for (int l = wid; l < Ll; l += 8) {
                        const float4* __restrict__ row = xb4 + (size_t)l * (Dd / 4);
                        float a0 = 0.f, a1 = 0.f, a2 = 0.f, a3 = 0.f;
                        #pragma unroll 4
                        for (int i = lane; i < Dd / 4; i += 32) {
                            float4 wv = wb4[i];
                            float4 xv = row[i];
                            a0 = fmaf(wv.x, xv.x, a0);
                            a1 = fmaf(wv.y, xv.y, a1);
                            a2 = fmaf(wv.z, xv.z, a2);
                            a3 = fmaf(wv.w, xv.w, a3);
                        }
                        float acc = (a0 + a1) + (a2 + a3);
                        #pragma unroll
                        for (int o = 16; o > 0; o >>= 1) acc += __shfl_xor_sync(0xFFFFFFFFu, acc, o);
                        if (lane == 0) yv[l] = acc * invZ;
                    }
                }
                BARA();

                // inline head on warp 0
                if (wid == 0) {
                    float z0 = sbp[lane], z1 = sbp[lane + 32];
                    #pragma unroll
                    for (int l = 0; l < Ll; ++l) {
                        const float y = yv[l];
                        z0 = fmaf(sWp[lane * Ll + l], y, z0);
                        z1 = fmaf(sWp[(lane + 32) * Ll + l], y, z1);
                    }
                    float sum = z0 + z1;
                    #pragma unroll
                    for (int o = 16; o > 0; o >>= 1) sum += __shfl_xor_sync(0xFFFFFFFFu, sum, o);
                    const float mu = sum * (1.f / 64.f);
                    const float d0 = z0 - mu, d1 = z1 - mu;
                    float sq = d0 * d0 + d1 * d1;
                    #pragma unroll
                    for (int o = 16; o > 0; o >>= 1) sq += __shfl_xor_sync(0xFFFFFFFFu, sq, o);
                    const float rstd = rsqrtf(sq * (1.f / 64.f) + 1e-5f);
                    zz[lane]      = d0 * rstd * sg[lane] + sbe[lane];
                    zz[lane + 32] = d1 * rstd * sg[lane + 32] + sbe[lane + 32];
                    __syncwarp();

                    float a[4];
                    #pragma unroll
                    for (int k = 0; k < 4; ++k) {
                        const int jj = k * 32 + lane;
                        float acc = sb1[jj];
                        #pragma unroll
                        for (int p = 0; p < Pp; ++p) {
                            const int pr = (p + lane) & (Pp - 1);
                            acc = fmaf(sW1[jj * Pp + pr], zz[pr], acc);
                        }
                        a[k] = 0.5f * acc * (1.f + erff(acc * 0.70710678118654752f)); // exact GELU
                    }
                    float o0 = 0.f, o1 = 0.f;
                    #pragma unroll
                    for (int k = 0; k < 4; ++k) {
                        const int jj = k * 32 + lane;
                        o0 = fmaf(sW2[jj], a[k], o0);
                        o1 = fmaf(sW2[Hh + jj], a[k], o1);
                    }
                    #pragma unroll
                    for (int o = 16; o > 0; o >>= 1) {
                        o0 += __shfl_xor_sync(0xFFFFFFFFu, o0, o);
                        o1 += __shfl_xor_sync(0xFFFFFFFFu, o1, o);
                    }
                    if (lane == 0) {
                        out[(b0 + j) * 2 + 0] = o0 + b2[0];
                        out[(b0 + j) * 2 + 1] = o1 + b2[1];
                    }
                }
            }
        }
        __syncthreads();  // step boundary: buffer handoff
    }
}

extern "C" void kernel_launch(void* const* d_in, const int* in_sizes, int n_in,
                              void* d_out, int out_size) {
    const float* x     = (const float*)d_in[0];
    const float* Wp    = (const float*)d_in[1];
    const float* bp    = (const float*)d_in[2];
    const float* ws    = (const float*)d_in[3];
    const float* bsc   = (const float*)d_in[4];
    const float* gamma = (const float*)d_in[5];
    const float* beta  = (const float*)d_in[6];
    const float* W1    = (const float*)d_in[7];
    const float* b1    = (const float*)d_in[8];
    const float* W2    = (const float*)d_in[9];
    const float* b2    = (const float*)d_in[10];
    float* out = (float*)d_out;

    cudaFuncSetAttribute(mega_kernel, cudaFuncAttributeMaxDynamicSharedMemorySize, SMEM_BYTES);
    mega_kernel<<<GRID, NTM, SMEM_BYTES>>>(x, Wp, bp, ws, bsc, gamma, beta, W1, b1, W2, b2, out);
}

// round 13
// speedup vs baseline: 1.5176x; 1.5176x over previous
#include <cuda_runtime.h>
#include <math.h>

// SparseDimAttention, GB300 sm_103a — R9 mega (single x DRAM read + L2 re-read)
// + lean per-batch head (grid=512, latency hidden by concurrency).

constexpr int Ll = 33, Dd = 4096, Pp = 64, Kk = 512, Hh = 128, Bb = 512;
constexpr int BINS = 1024;

__device__ float g_y[(size_t)Bb * Ll];

__device__ __forceinline__ unsigned int fkey(float f) {
    unsigned int u = __float_as_uint(f);
    return u ^ ((u & 0x80000000u) ? 0xFFFFFFFFu : 0x80000000u); // ascending monotonic
}

// ---------------- mega (identical to R9) ----------------
#define NTM 512
constexpr int CHM = Dd / NTM;      // 8
constexpr int BPTM = BINS / NTM;   // 2
constexpr int TREPM = BINS / NTM;  // 2
constexpr int SMEM_BYTES = 128 * 1024;  // forces 1 CTA/SM

__global__ void __launch_bounds__(NTM, 1) mega_kernel(
    const float* __restrict__ x, const float* __restrict__ Wp,
    const float* __restrict__ bp, const float* __restrict__ ws,
    const float* __restrict__ bsc)
{
    extern __shared__ float dyn[];
    float* sc = dyn;                         // [Dd] scores -> weights
    int* hist = (int*)(dyn + Dd);            // [BINS]

    __shared__ float v[Ll];
    __shared__ float redmx[16], redmn[16], redf[16];
    __shared__ int   wsum_[16];
    __shared__ float s_c, s_m, s_lo, s_scale, s_invZ;
    __shared__ int   s_thr, s_rem, s_cnt, s_T;

    const int b = blockIdx.x, tid = threadIdx.x;
    const int lane = tid & 31, wid = tid >> 5;

    if (tid < Ll) {
        float a = 0.f;
        #pragma unroll
        for (int p = 0; p < Pp; ++p) a = fmaf(ws[p], Wp[p * Ll + tid], a);
        v[tid] = a;
    } else if (tid == Ll) {
        float a = bsc[0];
        #pragma unroll
        for (int p = 0; p < Pp; ++p) a = fmaf(ws[p], bp[p], a);
        s_c = a;
    }
    #pragma unroll
    for (int j = 0; j < BPTM; ++j) hist[j * NTM + tid] = 0;
    if (tid == 0) s_cnt = 0;
    __syncthreads();

    const float4* __restrict__ xb4 =
        reinterpret_cast<const float4*>(x) + (size_t)b * Ll * (Dd / 4);

    // ---- phase 1: stream x[b] from DRAM, scores into smem ----
    {
        const float cc = s_c;
        float4 a0 = make_float4(cc, cc, cc, cc);
        float4 a1 = make_float4(cc, cc, cc, cc);
        #pragma unroll 4
        for (int l = 0; l < Ll; ++l) {
            const float vl = v[l];
            const float4* row = xb4 + (size_t)l * (Dd / 4);
            float4 x0 = row[tid];
            float4 x1 = row[tid + NTM];
            a0.x = fmaf(vl, x0.x, a0.x); a0.y = fmaf(vl, x0.y, a0.y);
            a0.z = fmaf(vl, x0.z, a0.z); a0.w = fmaf(vl, x0.w, a0.w);
            a1.x = fmaf(vl, x1.x, a1.x); a1.y = fmaf(vl, x1.y, a1.y);
            a1.z = fmaf(vl, x1.z, a1.z); a1.w = fmaf(vl, x1.w, a1.w);
        }
        float4* sc4 = reinterpret_cast<float4*>(sc);
        sc4[tid] = a0;
        sc4[tid + NTM] = a1;
        float mx = fmaxf(fmaxf(a0.x, a0.y), fmaxf(a0.z, a0.w));
        mx = fmaxf(mx, fmaxf(fmaxf(a1.x, a1.y), fmaxf(a1.z, a1.w)));
        float mn = fminf(fminf(a0.x, a0.y), fminf(a0.z, a0.w));
        mn = fminf(mn, fminf(fminf(a1.x, a1.y), fminf(a1.z, a1.w)));
        #pragma unroll
        for (int o = 16; o > 0; o >>= 1) {
            mx = fmaxf(mx, __shfl_xor_sync(0xFFFFFFFFu, mx, o));
            mn = fminf(mn, __shfl_xor_sync(0xFFFFFFFFu, mn, o));
        }
        if (lane == 0) { redmx[wid] = mx; redmn[wid] = mn; }
    }
    __syncthreads();
    if (tid < 16) {
        float mx = redmx[tid], mn = redmn[tid];
        #pragma unroll
        for (int o = 8; o > 0; o >>= 1) {
            mx = fmaxf(mx, __shfl_xor_sync(0x0000FFFFu, mx, o));
            mn = fminf(mn, __shfl_xor_sync(0x0000FFFFu, mn, o));
        }
        if (tid == 0) {
            s_m = mx; s_lo = mn;
            const float r = mx - mn;
            s_scale = (r > 0.f) ? ((float)(BINS - 1) / r) : 0.f;
        }
    }
    __syncthreads();

    const float lo = s_lo, scale = s_scale, mm = s_m;
    #pragma unroll
    for (int it = 0; it < CHM; ++it) {
        const float s = sc[it * NTM + tid];
        int bin = (int)((s - lo) * scale);
        bin = min(BINS - 1, max(0, bin));
        atomicAdd(&hist[bin], 1);
    }
    __syncthreads();

    // suffix scan: hist[i] = #elements with bin >= i
    {
        const int base = tid * BPTM;
        int c[BPTM];
        #pragma unroll
        for (int j = 0; j < BPTM; ++j) c[j] = hist[base + j];
        #pragma unroll
        for (int j = BPTM - 2; j >= 0; --j) c[j] += c[j + 1];
        int inc = c[0];
        #pragma unroll
        for (int o = 1; o < 32; o <<= 1) {
            int t = __shfl_up_sync(0xFFFFFFFFu, inc, o);
            if (lane >= o) inc += t;
        }
        if (lane == 31) wsum_[wid] = inc;
        __syncthreads();
        if (tid < 16) {
            int w = wsum_[tid];
            int iw = w;
            #pragma unroll
            for (int o = 1; o < 16; o <<= 1) {
                int t = __shfl_up_sync(0x0000FFFFu, iw, o);
                if (tid >= o) iw += t;
            }
            wsum_[tid] = iw - w;
            if (tid == 15) s_T = iw;
        }
        __syncthreads();
        const int S = s_T - (wsum_[wid] + inc);
        #pragma unroll
        for (int j = 0; j < BPTM; ++j) hist[base + j] = S + c[j];
    }
    __syncthreads();

    #pragma unroll
    for (int j = 0; j < BPTM; ++j) {
        const int i = tid * BPTM + j;
        const int hv = hist[i];
        const int nx = (i < BINS - 1) ? hist[i + 1] : 0;
        if (hv >= Kk && nx < Kk) { s_thr = i; s_rem = Kk - nx; }
    }
    __syncthreads();
    const int thr = s_thr, rem = s_rem;

    #pragma unroll
    for (int it = 0; it < CHM; ++it) {
        const int d = it * NTM + tid;
        int bin = (int)((sc[d] - lo) * scale);
        bin = min(BINS - 1, max(0, bin));
        if (bin == thr) {
            int pos = atomicAdd(&s_cnt, 1);
            if (pos < BINS) hist[pos] = d;
        }
    }
    __syncthreads();
    const int cnt = s_cnt;
    const bool fast = (cnt <= BINS);

    float sv[CHM];
    #pragma unroll
    for (int it = 0; it < CHM; ++it) sv[it] = sc[it * NTM + tid];

    float twl[TREPM]; int tdl[TREPM];
    float twf[CHM];
    if (fast) {
        #pragma unroll
        for (int rep = 0; rep < TREPM; ++rep) {
            const int i = rep * NTM + tid;
            twl[rep] = 0.f; tdl[rep] = -1;
            if (i < cnt) {
                const int d = hist[i];
                const float s = sc[d];
                const unsigned int ke = fkey(s);
                int rank = 0;
                for (int j2 = 0; j2 < cnt; ++j2) {
                    const int d2 = hist[j2];
                    const unsigned int k2 = fkey(sc[d2]);
                    rank += (k2 > ke) || (k2 == ke && d2 < d);
                }
                tdl[rep] = d;
                twl[rep] = (rank < rem) ? expf(s - mm) : 0.f;
            }
        }
    } else {
        #pragma unroll
        for (int it = 0; it < CHM; ++it) {
            const int d = it * NTM + tid;
            int bin = (int)((sv[it] - lo) * scale);
            bin = min(BINS - 1, max(0, bin));
            twf[it] = 0.f;
            if (bin == thr) {
                const unsigned int ke = fkey(sv[it]);
                int rank = 0;
                for (int d2 = 0; d2 < Dd; ++d2) {
                    const float s2 = sc[d2];
                    int b2i = (int)((s2 - lo) * scale);
                    b2i = min(BINS - 1, max(0, b2i));
                    if (b2i == thr) {
                        const unsigned int k2 = fkey(s2);
                        rank += (k2 > ke) || (k2 == ke && d2 < d);
                    }
                }
                twf[it] = (rank < rem) ? expf(sv[it] - mm) : 0.f;
            }
        }
    }
    __syncthreads();

    float zp = 0.f;
    #pragma unroll
    for (int it = 0; it < CHM; ++it) {
        const int d = it * NTM + tid;
        int bin = (int)((sv[it] - lo) * scale);
        bin = min(BINS - 1, max(0, bin));
        if (bin != thr) {
            const float w = (bin > thr) ? expf(sv[it] - mm) : 0.f;
            sc[d] = w; zp += w;
        } else if (!fast) {
            sc[d] = twf[it]; zp += twf[it];
        }
    }
    if (fast) {
        #pragma unroll
        for (int rep = 0; rep < TREPM; ++rep)
            if (tdl[rep] >= 0) { sc[tdl[rep]] = twl[rep]; zp += twl[rep]; }
    }
    #pragma unroll
    for (int o = 16; o > 0; o >>= 1) zp += __shfl_xor_sync(0xFFFFFFFFu, zp, o);
    if (lane == 0) redf[wid] = zp;
    __syncthreads();
    if (tid < 16) {
        zp = redf[tid];
        #pragma unroll
        for (int o = 8; o > 0; o >>= 1) zp += __shfl_xor_sync(0x0000FFFFu, zp, o);
        if (tid == 0) s_invZ = 1.f / zp;
    }
    __syncthreads();

    // ---- phase 5: y[l] = invZ * sum_d w[d]*x[b,l,d]  (x[b] re-read from L2) ----
    {
        const float invZ = s_invZ;
        const float4* sc4 = reinterpret_cast<const float4*>(sc);
        for (int l = wid; l < Ll; l += 16) {
            const float4* __restrict__ row = xb4 + (size_t)l * (Dd / 4);
            float a0 = 0.f, a1 = 0.f, a2 = 0.f, a3 = 0.f;
            #pragma unroll 4
            for (int i = lane; i < Dd / 4; i += 32) {
                float4 wv = sc4[i];
                float4 xv = row[i];
                a0 = fmaf(wv.x, xv.x, a0);
                a1 = fmaf(wv.y, xv.y, a1);
                a2 = fmaf(wv.z, xv.z, a2);
                a3 = fmaf(wv.w, xv.w, a3);
            }
            float acc = (a0 + a1) + (a2 + a3);
            #pragma unroll
            for (int o = 16; o > 0; o >>= 1) acc += __shfl_xor_sync(0xFFFFFFFFu, acc, o);
            if (lane == 0) g_y[(size_t)b * Ll + l] = acc * invZ;
        }
    }
}

// ---------------- head: one CTA per batch, 128 threads ----------------
__global__ void __launch_bounds__(128) head_kernel(
    const float* __restrict__ Wp, const float* __restrict__ bp,
    const float* __restrict__ gamma, const float* __restrict__ beta,
    const float* __restrict__ W1, const float* __restrict__ b1,
    const float* __restrict__ W2, const float* __restrict__ b2,
    float* __restrict__ out)
{
    __shared__ float sW1p[Hh * (Pp + 1)];   // padded stride 65 -> conflict-free
    __shared__ float yv[Ll];
    __shared__ float zz[Pp];
    __shared__ float aa[Hh];
    __shared__ float s_mu, s_rstd;
    const int b = blockIdx.x;
    const int tid = threadIdx.x;
    const int lane = tid & 31, wid = tid >> 5;

    // stage W1 coalesced into padded smem (L2-resident after first CTAs)
    for (int i = tid; i < Hh * Pp; i += 128) {
        const int h = i >> 6, p = i & 63;
        sW1p[h * (Pp + 1) + p] = W1[i];
    }
    if (tid < Ll) yv[tid] = g_y[(size_t)b * Ll + tid];
    __syncthreads();

    // z = Wp@y + bp (threads 0-63; Wp is 8.4KB, L2-resident)
    if (tid < Pp) {
        float acc = bp[tid];
        #pragma unroll
        for (int l = 0; l < Ll; ++l) acc = fmaf(Wp[tid * Ll + l], yv[l], acc);
        zz[tid] = acc;
    }
    __syncthreads();

    // LayerNorm stats on warp 0 (2 values per lane)
    if (tid < 32) {
        float a = zz[tid], bq = zz[tid + 32];
        float sum = a + bq;
        #pragma unroll
        for (int o = 16; o > 0; o >>= 1) sum += __shfl_xor_sync(0xFFFFFFFFu, sum, o);
        const float mu = sum * (1.f / 64.f);
        const float da = a - mu, db = bq - mu;
        float sq = da * da + db * db;
        #pragma unroll
        for (int o = 16; o > 0; o >>= 1) sq += __shfl_xor_sync(0xFFFFFFFFu, sq, o);
        if (tid == 0) { s_mu = mu; s_rstd = rsqrtf(sq * (1.f / 64.f) + 1e-5f); }
    }
    __syncthreads();
    if (tid < Pp) zz[tid] = (zz[tid] - s_mu) * s_rstd * gamma[tid] + beta[tid];
    __syncthreads();

    // W1 + exact GELU: thread t computes h=t. sW1p bank = (h + p) % 32 -> conflict-free;
    // zz[p] same address across warp -> broadcast.
    {
        float acc = b1[tid];
        #pragma unroll
        for (int p = 0; p < Pp; ++p)
            acc = fmaf(sW1p[tid * (Pp + 1) + p], zz[p], acc);
        aa[tid] = 0.5f * acc * (1.f + erff(acc * 0.70710678118654752f));
    }
    __syncthreads();

    // W2: warps 0 and 1 reduce one output each
    if (wid < 2) {
        float acc = 0.f;
        #pragma unroll
        for (int k = 0; k < 4; ++k) {
            const int j = k * 32 + lane;
            acc = fmaf(W2[wid * Hh + j], aa[j], acc);
        }
        #pragma unroll
        for (int o = 16; o > 0; o >>= 1) acc += __shfl_xor_sync(0xFFFFFFFFu, acc, o);
        if (lane == 0) out[b * 2 + wid] = acc + b2[wid];
    }
}

extern "C" void kernel_launch(void* const* d_in, const int* in_sizes, int n_in,
                              void* d_out, int out_size) {
    const float* x     = (const float*)d_in[0];
    const float* Wp    = (const float*)d_in[1];
    const float* bp    = (const float*)d_in[2];
    const float* ws    = (const float*)d_in[3];
    const float* bsc   = (const float*)d_in[4];
    const float* gamma = (const float*)d_in[5];
    const float* beta  = (const float*)d_in[6];
    const float* W1    = (const float*)d_in[7];
    const float* b1    = (const float*)d_in[8];
    const float* W2    = (const float*)d_in[9];
    const float* b2    = (const float*)d_in[10];
    float* out = (float*)d_out;

    cudaFuncSetAttribute(mega_kernel, cudaFuncAttributeMaxDynamicSharedMemorySize, SMEM_BYTES);
    mega_kernel<<<Bb, NTM, SMEM_BYTES>>>(x, Wp, bp, ws, bsc);
    head_kernel<<<Bb, 128>>>(Wp, bp, gamma, beta, W1, b1, W2, b2, out);
}

// round 14
// speedup vs baseline: 1.6054x; 1.0579x over previous
#include <cuda_runtime.h>
#include <math.h>

// SparseDimAttention, GB300 sm_103a — R9 mega (single x DRAM read + L2 re-read)
// + PDL-overlapped head: head CTAs pre-stage weights in smem during mega's last
//   wave (programmatic stream serialization), then gridDependencySync -> ~1us compute.

constexpr int Ll = 33, Dd = 4096, Pp = 64, Kk = 512, Hh = 128, Bb = 512;
constexpr int BINS = 1024;

__device__ float g_y[(size_t)Bb * Ll];

__device__ __forceinline__ unsigned int fkey(float f) {
    unsigned int u = __float_as_uint(f);
    return u ^ ((u & 0x80000000u) ? 0xFFFFFFFFu : 0x80000000u); // ascending monotonic
}

// ---------------- mega (identical to R9/R13) ----------------
#define NTM 512
constexpr int CHM = Dd / NTM;      // 8
constexpr int BPTM = BINS / NTM;   // 2
constexpr int TREPM = BINS / NTM;  // 2
constexpr int SMEM_BYTES = 128 * 1024;  // forces 1 CTA/SM

__global__ void __launch_bounds__(NTM, 1) mega_kernel(
    const float* __restrict__ x, const float* __restrict__ Wp,
    const float* __restrict__ bp, const float* __restrict__ ws,
    const float* __restrict__ bsc)
{
    extern __shared__ float dyn[];
    float* sc = dyn;                         // [Dd] scores -> weights
    int* hist = (int*)(dyn + Dd);            // [BINS]

    __shared__ float v[Ll];
    __shared__ float redmx[16], redmn[16], redf[16];
    __shared__ int   wsum_[16];
    __shared__ float s_c, s_m, s_lo, s_scale, s_invZ;
    __shared__ int   s_thr, s_rem, s_cnt, s_T;

    const int b = blockIdx.x, tid = threadIdx.x;
    const int lane = tid & 31, wid = tid >> 5;

    if (tid < Ll) {
        float a = 0.f;
        #pragma unroll
        for (int p = 0; p < Pp; ++p) a = fmaf(ws[p], Wp[p * Ll + tid], a);
        v[tid] = a;
    } else if (tid == Ll) {
        float a = bsc[0];
        #pragma unroll
        for (int p = 0; p < Pp; ++p) a = fmaf(ws[p], bp[p], a);
        s_c = a;
    }
    #pragma unroll
    for (int j = 0; j < BPTM; ++j) hist[j * NTM + tid] = 0;
    if (tid == 0) s_cnt = 0;
    __syncthreads();

    const float4* __restrict__ xb4 =
        reinterpret_cast<const float4*>(x) + (size_t)b * Ll * (Dd / 4);

    // ---- phase 1: stream x[b] from DRAM, scores into smem ----
    {
        const float cc = s_c;
        float4 a0 = make_float4(cc, cc, cc, cc);
        float4 a1 = make_float4(cc, cc, cc, cc);
        #pragma unroll 4
        for (int l = 0; l < Ll; ++l) {
            const float vl = v[l];
            const float4* row = xb4 + (size_t)l * (Dd / 4);
            float4 x0 = row[tid];
            float4 x1 = row[tid + NTM];
            a0.x = fmaf(vl, x0.x, a0.x); a0.y = fmaf(vl, x0.y, a0.y);
            a0.z = fmaf(vl, x0.z, a0.z); a0.w = fmaf(vl, x0.w, a0.w);
            a1.x = fmaf(vl, x1.x, a1.x); a1.y = fmaf(vl, x1.y, a1.y);
            a1.z = fmaf(vl, x1.z, a1.z); a1.w = fmaf(vl, x1.w, a1.w);
        }
        float4* sc4 = reinterpret_cast<float4*>(sc);
        sc4[tid] = a0;
        sc4[tid + NTM] = a1;
        float mx = fmaxf(fmaxf(a0.x, a0.y), fmaxf(a0.z, a0.w));
        mx = fmaxf(mx, fmaxf(fmaxf(a1.x, a1.y), fmaxf(a1.z, a1.w)));
        float mn = fminf(fminf(a0.x, a0.y), fminf(a0.z, a0.w));
        mn = fminf(mn, fminf(fminf(a1.x, a1.y), fminf(a1.z, a1.w)));
        #pragma unroll
        for (int o = 16; o > 0; o >>= 1) {
            mx = fmaxf(mx, __shfl_xor_sync(0xFFFFFFFFu, mx, o));
            mn = fminf(mn, __shfl_xor_sync(0xFFFFFFFFu, mn, o));
        }
        if (lane == 0) { redmx[wid] = mx; redmn[wid] = mn; }
    }
    __syncthreads();
    if (tid < 16) {
        float mx = redmx[tid], mn = redmn[tid];
        #pragma unroll
        for (int o = 8; o > 0; o >>= 1) {
            mx = fmaxf(mx, __shfl_xor_sync(0x0000FFFFu, mx, o));
            mn = fminf(mn, __shfl_xor_sync(0x0000FFFFu, mn, o));
        }
        if (tid == 0) {
            s_m = mx; s_lo = mn;
            const float r = mx - mn;
            s_scale = (r > 0.f) ? ((float)(BINS - 1) / r) : 0.f;
        }
    }
    __syncthreads();

    const float lo = s_lo, scale = s_scale, mm = s_m;
    #pragma unroll
    for (int it = 0; it < CHM; ++it) {
        const float s = sc[it * NTM + tid];
        int bin = (int)((s - lo) * scale);
        bin = min(BINS - 1, max(0, bin));
        atomicAdd(&hist[bin], 1);
    }
    __syncthreads();

    // suffix scan: hist[i] = #elements with bin >= i
    {
        const int base = tid * BPTM;
        int c[BPTM];
        #pragma unroll
        for (int j = 0; j < BPTM; ++j) c[j] = hist[base + j];
        #pragma unroll
        for (int j = BPTM - 2; j >= 0; --j) c[j] += c[j + 1];
        int inc = c[0];
        #pragma unroll
        for (int o = 1; o < 32; o <<= 1) {
            int t = __shfl_up_sync(0xFFFFFFFFu, inc, o);
            if (lane >= o) inc += t;
        }
        if (lane == 31) wsum_[wid] = inc;
        __syncthreads();
        if (tid < 16) {
            int w = wsum_[tid];
            int iw = w;
            #pragma unroll
            for (int o = 1; o < 16; o <<= 1) {
                int t = __shfl_up_sync(0x0000FFFFu, iw, o);
                if (tid >= o) iw += t;
            }
            wsum_[tid] = iw - w;
            if (tid == 15) s_T = iw;
        }
        __syncthreads();
        const int S = s_T - (wsum_[wid] + inc);
        #pragma unroll
        for (int j = 0; j < BPTM; ++j) hist[base + j] = S + c[j];
    }
    __syncthreads();

    #pragma unroll
    for (int j = 0; j < BPTM; ++j) {
        const int i = tid * BPTM + j;
        const int hv = hist[i];
        const int nx = (i < BINS - 1) ? hist[i + 1] : 0;
        if (hv >= Kk && nx < Kk) { s_thr = i; s_rem = Kk - nx; }
    }
    __syncthreads();
    const int thr = s_thr, rem = s_rem;

    #pragma unroll
    for (int it = 0; it < CHM; ++it) {
        const int d = it * NTM + tid;
        int bin = (int)((sc[d] - lo) * scale);
        bin = min(BINS - 1, max(0, bin));
        if (bin == thr) {
            int pos = atomicAdd(&s_cnt, 1);
            if (pos < BINS) hist[pos] = d;
        }
    }
    __syncthreads();
    const int cnt = s_cnt;
    const bool fast = (cnt <= BINS);

    float sv[CHM];
    #pragma unroll
    for (int it = 0; it < CHM; ++it) sv[it] = sc[it * NTM + tid];

    float twl[TREPM]; int tdl[TREPM];
    float twf[CHM];
    if (fast) {
        #pragma unroll
        for (int rep = 0; rep < TREPM; ++rep) {
            const int i = rep * NTM + tid;
            twl[rep] = 0.f; tdl[rep] = -1;
            if (i < cnt) {
                const int d = hist[i];
                const float s = sc[d];
                const unsigned int ke = fkey(s);
                int rank = 0;
                for (int j2 = 0; j2 < cnt; ++j2) {
                    const int d2 = hist[j2];
                    const unsigned int k2 = fkey(sc[d2]);
                    rank += (k2 > ke) || (k2 == ke && d2 < d);
                }
                tdl[rep] = d;
                twl[rep] = (rank < rem) ? expf(s - mm) : 0.f;
            }
        }
    } else {
        #pragma unroll
        for (int it = 0; it < CHM; ++it) {
            const int d = it * NTM + tid;
            int bin = (int)((sv[it] - lo) * scale);
            bin = min(BINS - 1, max(0, bin));
            twf[it] = 0.f;
            if (bin == thr) {
                const unsigned int ke = fkey(sv[it]);
                int rank = 0;
                for (int d2 = 0; d2 < Dd; ++d2) {
                    const float s2 = sc[d2];
                    int b2i = (int)((s2 - lo) * scale);
                    b2i = min(BINS - 1, max(0, b2i));
                    if (b2i == thr) {
                        const unsigned int k2 = fkey(s2);
                        rank += (k2 > ke) || (k2 == ke && d2 < d);
                    }
                }
                twf[it] = (rank < rem) ? expf(sv[it] - mm) : 0.f;
            }
        }
    }
    __syncthreads();

    float zp = 0.f;
    #pragma unroll
    for (int it = 0; it < CHM; ++it) {
        const int d = it * NTM + tid;
        int bin = (int)((sv[it] - lo) * scale);
        bin = min(BINS - 1, max(0, bin));
        if (bin != thr) {
            const float w = (bin > thr) ? expf(sv[it] - mm) : 0.f;
            sc[d] = w; zp += w;
        } else if (!fast) {
            sc[d] = twf[it]; zp += twf[it];
        }
    }
    if (fast) {
        #pragma unroll
        for (int rep = 0; rep < TREPM; ++rep)
            if (tdl[rep] >= 0) { sc[tdl[rep]] = twl[rep]; zp += twl[rep]; }
    }
    #pragma unroll
    for (int o = 16; o > 0; o >>= 1) zp += __shfl_xor_sync(0xFFFFFFFFu, zp, o);
    if (lane == 0) redf[wid] = zp;
    __syncthreads();
    if (tid < 16) {
        zp = redf[tid];
        #pragma unroll
        for (int o = 8; o > 0; o >>= 1) zp += __shfl_xor_sync(0x0000FFFFu, zp, o);
        if (tid == 0) s_invZ = 1.f / zp;
    }
    __syncthreads();

    // ---- phase 5: y[l] = invZ * sum_d w[d]*x[b,l,d]  (x[b] re-read from L2) ----
    {
        const float invZ = s_invZ;
        const float4* sc4 = reinterpret_cast<const float4*>(sc);
        for (int l = wid; l < Ll; l += 16) {
            const float4* __restrict__ row = xb4 + (size_t)l * (Dd / 4);
            float a0 = 0.f, a1 = 0.f, a2 = 0.f, a3 = 0.f;
            #pragma unroll 4
            for (int i = lane; i < Dd / 4; i += 32) {
                float4 wv = sc4[i];
                float4 xv = row[i];
                a0 = fmaf(wv.x, xv.x, a0);
                a1 = fmaf(wv.y, xv.y, a1);
                a2 = fmaf(wv.z, xv.z, a2);
                a3 = fmaf(wv.w, xv.w, a3);
            }
            float acc = (a0 + a1) + (a2 + a3);
            #pragma unroll
            for (int o = 16; o > 0; o >>= 1) acc += __shfl_xor_sync(0xFFFFFFFFu, acc, o);
            if (lane == 0) g_y[(size_t)b * Ll + l] = acc * invZ;
        }
    }
}

// ---------------- head: PDL-overlapped, one CTA per batch ----------------
__global__ void __launch_bounds__(128) head_kernel(
    const float* __restrict__ Wp, const float* __restrict__ bp,
    const float* __restrict__ gamma, const float* __restrict__ beta,
    const float* __restrict__ W1, const float* __restrict__ b1,
    const float* __restrict__ W2, const float* __restrict__ b2,
    float* __restrict__ out)
{
    __shared__ float sW1p[Hh * (Pp + 1)];   // padded stride 65 -> conflict-free compute
    __shared__ float sWp[Pp * Ll];          // stride 33 (odd) -> conflict-free compute
    __shared__ float sbp[Pp], sg[Pp], sbe[Pp], sb1[Hh], sW2[2 * Hh], sb2v[2];
    __shared__ float yv[Ll], zz[Pp], aa[Hh];
    __shared__ float s_mu, s_rstd;
    const int b = blockIdx.x;
    const int tid = threadIdx.x;
    const int lane = tid & 31, wid = tid >> 5;

    // ======== PRE-SYNC: stage all weights (overlaps mega's last wave) ========
    {
        const float4* W14 = reinterpret_cast<const float4*>(W1);
        #pragma unroll
        for (int i = tid; i < Hh * Pp / 4; i += 128) {   // 16 independent float4 loads
            float4 w = W14[i];
            const int h = i >> 4, q = i & 15;
            const int base = h * (Pp + 1) + q * 4;
            sW1p[base] = w.x; sW1p[base + 1] = w.y; sW1p[base + 2] = w.z; sW1p[base + 3] = w.w;
        }
    }
    for (int i = tid; i < Pp * Ll; i += 128) sWp[i] = Wp[i];
    if (tid < Pp) { sbp[tid] = bp[tid]; sg[tid] = gamma[tid]; sbe[tid] = beta[tid]; }
    if (tid < Hh) sb1[tid] = b1[tid];
    #pragma unroll
    for (int k = 0; k < 2; ++k) sW2[k * 128 + tid] = W2[k * 128 + tid];
    if (tid < 2) sb2v[tid] = b2[tid];

    // ======== wait for mega's g_y writes ========
    cudaGridDependencySynchronize();

    if (tid < Ll) yv[tid] = g_y[(size_t)b * Ll + tid];   // L2-hot (mega just wrote)
    __syncthreads();

    // z = Wp@y + bp
    if (tid < Pp) {
        float acc = sbp[tid];
        #pragma unroll
        for (int l = 0; l < Ll; ++l) acc = fmaf(sWp[tid * Ll + l], yv[l], acc);
        zz[tid] = acc;
    }
    __syncthreads();

    if (tid < 32) {
        float a = zz[tid], bq = zz[tid + 32];
        float sum = a + bq;
        #pragma unroll
        for (int o = 16; o > 0; o >>= 1) sum += __shfl_xor_sync(0xFFFFFFFFu, sum, o);
        const float mu = sum * (1.f / 64.f);
        const float da = a - mu, db = bq - mu;
        float sq = da * da + db * db;
        #pragma unroll
        for (int o = 16; o > 0; o >>= 1) sq += __shfl_xor_sync(0xFFFFFFFFu, sq, o);
        if (tid == 0) { s_mu = mu; s_rstd = rsqrtf(sq * (1.f / 64.f) + 1e-5f); }
    }
    __syncthreads();
    if (tid < Pp) zz[tid] = (zz[tid] - s_mu) * s_rstd * sg[tid] + sbe[tid];
    __syncthreads();

    // W1 + exact GELU: thread t computes h=t; bank = (h + p) % 32 -> conflict-free
    {
        float acc = sb1[tid];
        #pragma unroll
        for (int p = 0; p < Pp; ++p)
            acc = fmaf(sW1p[tid * (Pp + 1) + p], zz[p], acc);
        aa[tid] = 0.5f * acc * (1.f + erff(acc * 0.70710678118654752f));
    }
    __syncthreads();

    if (wid < 2) {
        float acc = 0.f;
        #pragma unroll
        for (int k = 0; k < 4; ++k) {
            const int j = k * 32 + lane;
            acc = fmaf(sW2[wid * Hh + j], aa[j], acc);
        }
        #pragma unroll
        for (int o = 16; o > 0; o >>= 1) acc += __shfl_xor_sync(0xFFFFFFFFu, acc, o);
        if (lane == 0) out[b * 2 + wid] = acc + sb2v[wid];
    }
}

extern "C" void kernel_launch(void* const* d_in, const int* in_sizes, int n_in,
                              void* d_out, int out_size) {
    const float* x     = (const float*)d_in[0];
    const float* Wp    = (const float*)d_in[1];
    const float* bp    = (const float*)d_in[2];
    const float* ws    = (const float*)d_in[3];
    const float* bsc   = (const float*)d_in[4];
    const float* gamma = (const float*)d_in[5];
    const float* beta  = (const float*)d_in[6];
    const float* W1    = (const float*)d_in[7];
    const float* b1    = (const float*)d_in[8];
    const float* W2    = (const float*)d_in[9];
    const float* b2    = (const float*)d_in[10];
    float* out = (float*)d_out;

    cudaFuncSetAttribute(mega_kernel, cudaFuncAttributeMaxDynamicSharedMemorySize, SMEM_BYTES);
    mega_kernel<<<Bb, NTM, SMEM_BYTES>>>(x, Wp, bp, ws, bsc);

    // PDL: head launches while mega drains; gridDependencySync orders g_y access.
    cudaLaunchConfig_t cfg = {};
    cfg.gridDim = dim3(Bb);
    cfg.blockDim = dim3(128);
    cfg.dynamicSmemBytes = 0;
    cfg.stream = 0;
    cudaLaunchAttribute attr[1];
    attr[0].id = cudaLaunchAttributeProgrammaticStreamSerialization;
    attr[0].val.programmaticStreamSerializationAllowed = 1;
    cfg.attrs = attr;
    cfg.numAttrs = 1;
    cudaLaunchKernelEx(&cfg, head_kernel, Wp, bp, gamma, beta, W1, b1, W2, b2, out);
}